// round 9
// baseline (speedup 1.0000x reference)
#include <cuda_runtime.h>
#include <cuda_bf16.h>
#include <math.h>
#include <stdint.h>

#define B_    4
#define C_    512
#define NPIX  4096
#define GROUPS 32
#define CPG   16

typedef __nv_bfloat16 bf16;

// ------------------- scratch (__device__ globals; allocation-free) ---------
__device__ bf16  g_hb[(size_t)B_ * NPIX * C_];          // h transposed (b,p,c)
__device__ bf16  g_w [(size_t)(3 * C_ * C_ + C_ * C_)]; // qkv_w ; out_w (bf16)
__device__ bf16  g_qk[(size_t)B_ * NPIX * 2 * C_];      // (b,p,o) o in [0,1024)
__device__ bf16  g_vt[(size_t)B_ * C_ * NPIX];          // (b,c,p)
__device__ bf16  g_p [(size_t)B_ * NPIX * NPIX];        // E = exp(scale*s) (b,i,j)
__device__ bf16  g_ao[(size_t)B_ * NPIX * C_];          // (b,i,c)
__device__ float g_S [(size_t)B_ * NPIX];               // row sums of E

// ------------------------------- helpers -----------------------------------
__device__ __forceinline__ uint32_t smem_u32(const void* p) {
    return (uint32_t)__cvta_generic_to_shared(p);
}
__device__ __forceinline__ void cp16(uint32_t dst, const void* src) {
    asm volatile("cp.async.cg.shared.global [%0], [%1], 16;\n" :: "r"(dst), "l"(src));
}
__device__ __forceinline__ void cp_commit() { asm volatile("cp.async.commit_group;\n"); }
template <int N> __device__ __forceinline__ void cp_wait() {
    asm volatile("cp.async.wait_group %0;\n" :: "n"(N));
}
__device__ __forceinline__ void ldsm4(uint32_t& r0, uint32_t& r1, uint32_t& r2, uint32_t& r3,
                                      uint32_t addr) {
    asm volatile("ldmatrix.sync.aligned.m8n8.x4.shared.b16 {%0,%1,%2,%3}, [%4];\n"
                 : "=r"(r0), "=r"(r1), "=r"(r2), "=r"(r3) : "r"(addr));
}
__device__ __forceinline__ void mma16816(float c[4],
                                         uint32_t a0, uint32_t a1, uint32_t a2, uint32_t a3,
                                         uint32_t b0, uint32_t b1) {
    asm volatile(
        "mma.sync.aligned.m16n8k16.row.col.f32.bf16.bf16.f32 "
        "{%0,%1,%2,%3},{%4,%5,%6,%7},{%8,%9},{%0,%1,%2,%3};\n"
        : "+f"(c[0]), "+f"(c[1]), "+f"(c[2]), "+f"(c[3])
        : "r"(a0), "r"(a1), "r"(a2), "r"(a3), "r"(b0), "r"(b1));
}

// --------------------------- fp32 -> bf16 convert ---------------------------
__global__ void f2bf_kernel(const float4* __restrict__ a, __nv_bfloat162* __restrict__ o, int n4)
{
    int i = blockIdx.x * 256 + threadIdx.x;
    if (i < n4) {
        float4 v = a[i];
        o[2 * i + 0] = __floats2bfloat162_rn(v.x, v.y);
        o[2 * i + 1] = __floats2bfloat162_rn(v.z, v.w);
    }
}

// --------------- GroupNorm + transpose: x(b,c,p) -> hb(b,p,c) bf16 ----------
__global__ void gn_t_kernel(const float* __restrict__ x,
                            const float* __restrict__ gw,
                            const float* __restrict__ gb,
                            bf16* __restrict__ hb)
{
    const int grp = blockIdx.x;
    const int b   = grp >> 5;
    const int g   = grp & 31;
    const float* xg = x + (size_t)grp * (CPG * NPIX);
    const int tid = threadIdx.x;

    float s = 0.f, ss = 0.f;
    const float4* x4 = (const float4*)xg;
    #pragma unroll 4
    for (int i = tid; i < (CPG * NPIX) / 4; i += 256) {
        float4 v = x4[i];
        s  += v.x + v.y + v.z + v.w;
        ss += v.x * v.x + v.y * v.y + v.z * v.z + v.w * v.w;
    }
    __shared__ float sh[64];
    #pragma unroll
    for (int o = 16; o; o >>= 1) {
        s  += __shfl_xor_sync(~0u, s, o);
        ss += __shfl_xor_sync(~0u, ss, o);
    }
    if ((tid & 31) == 0) { sh[tid >> 5] = s; sh[(tid >> 5) + 32] = ss; }
    __syncthreads();
    __shared__ float s_mu, s_rs;
    if (tid < 32) {
        float a = (tid < 8) ? sh[tid]      : 0.f;
        float c = (tid < 8) ? sh[tid + 32] : 0.f;
        #pragma unroll
        for (int o = 4; o; o >>= 1) {
            a += __shfl_xor_sync(~0u, a, o);
            c += __shfl_xor_sync(~0u, c, o);
        }
        if (tid == 0) {
            float mu  = a / (float)(CPG * NPIX);
            float var = c / (float)(CPG * NPIX) - mu * mu;
            s_mu = mu;
            s_rs = rsqrtf(var + 1e-5f);
        }
    }
    __syncthreads();

    __shared__ float s_sc[CPG], s_sb[CPG];
    if (tid < CPG) {
        float w = gw[g * CPG + tid] * s_rs;
        s_sc[tid] = w;
        s_sb[tid] = gb[g * CPG + tid] - s_mu * w;
    }
    __syncthreads();

    for (int p = tid; p < NPIX; p += 256) {
        __nv_bfloat162 pk[8];
        #pragma unroll
        for (int c2 = 0; c2 < 8; c2++) {
            float v0 = xg[(2 * c2 + 0) * NPIX + p] * s_sc[2 * c2 + 0] + s_sb[2 * c2 + 0];
            float v1 = xg[(2 * c2 + 1) * NPIX + p] * s_sc[2 * c2 + 1] + s_sb[2 * c2 + 1];
            pk[c2] = __floats2bfloat162_rn(v0, v1);
        }
        uint4* dst = (uint4*)(hb + ((size_t)(b * NPIX + p)) * C_ + g * CPG);
        dst[0] = *(uint4*)&pk[0];
        dst[1] = *(uint4*)&pk[4];
    }
}

// ------------- TN bf16 GEMM, mma.sync, 64x64 warp tile, 128 thr -------------
// MODE 0: normal (fp32 out w/ resid, or bf16 out, biases)
// MODE 1: bf16 out = exp(alpha * acc)
// MODE 2: bf16 out = acc * (1 / rowS[m])
#define BM 128
#define BN 128
#define BK 64
#define STAGES 3
#define ATILE (BM * BK)
#define STAGE_ELEMS ((BM + BN) * BK)
#define STAGE_BYTES (STAGE_ELEMS * 2)      // 32768
#define GTHREADS 128
#define GSMEM (STAGES * STAGE_BYTES)       // 98304 -> 2 CTAs/SM (smem-limited)

#define LOAD_STAGE(s_, kt_) do {                                                     \
    bf16* as_ = smem + (s_) * STAGE_ELEMS;                                           \
    bf16* bs_ = as_ + ATILE;                                                         \
    const bf16* ga_ = A  + (long long)(kt_) * BK + lchunk * 8;                       \
    const bf16* gb_ = Bm + (long long)(kt_) * BK + lchunk * 8;                       \
    _Pragma("unroll")                                                                \
    for (int p_ = 0; p_ < 8; p_++) {                                                 \
        int r_ = lrow + p_ * 16;                                                     \
        int sw_ = (lchunk ^ (r_ & 7)) << 4;                                          \
        cp16(smem_u32(as_) + (uint32_t)(r_ * (BK * 2)) + sw_,                        \
             ga_ + (long long)(m0 + r_) * lda);                                      \
        cp16(smem_u32(bs_) + (uint32_t)(r_ * (BK * 2)) + sw_,                        \
             gb_ + (long long)(n0 + r_) * ldb);                                      \
    }                                                                                \
} while (0)

template <int MODE>
__global__ void __launch_bounds__(GTHREADS)
bgemm_tn(const bf16* __restrict__ A, const bf16* __restrict__ Bm,
         float* __restrict__ Cf, bf16* __restrict__ Cb,
         int K, int lda, int ldb, int ldc,
         long long bA, long long bB, long long bC,
         float alpha,
         const float* __restrict__ biasM, const float* __restrict__ biasN,
         const float* __restrict__ resid,
         const float* __restrict__ rowS)
{
    extern __shared__ bf16 smem[];

    const int bz = blockIdx.z;
    A  += (long long)bz * bA;
    Bm += (long long)bz * bB;
    if (Cf)    Cf    += (long long)bz * bC;
    if (Cb)    Cb    += (long long)bz * bC;
    if (resid) resid += (long long)bz * bC;
    if (MODE == 2) rowS += (long long)bz * NPIX;

    const int m0   = blockIdx.y * BM;
    const int n0   = blockIdx.x * BN;
    const int tid  = threadIdx.x;
    const int lane = tid & 31;
    const int wid  = tid >> 5;           // 0..3
    const int wm   = (wid & 1) * 64;     // warp m-offset
    const int wn   = (wid >> 1) * 64;    // warp n-offset
    const int lrow   = tid >> 3;         // 0..15
    const int lchunk = tid & 7;          // 0..7
    const int nk = K / BK;

    // preload stages 0,1
    LOAD_STAGE(0, 0);
    cp_commit();
    if (nk > 1) LOAD_STAGE(1, 1);
    cp_commit();

    float acc[4][8][4] = {};

    int st = 0;
    for (int kt = 0; kt < nk; kt++) {
        cp_wait<STAGES - 2>();
        __syncthreads();                  // tile kt visible; stage (kt+2)%3 free

        if (kt + 2 < nk) LOAD_STAGE((kt + 2) % STAGES, kt + 2);
        cp_commit();

        const bf16* as = smem + st * STAGE_ELEMS;
        const bf16* bs = as + ATILE;
        const uint32_t sa = smem_u32(as);
        const uint32_t sb = smem_u32(bs);

        #pragma unroll
        for (int ks = 0; ks < 4; ks++) {
            uint32_t af[4][4], bfv[4][4];
            const uint32_t kc = (uint32_t)(ks * 2) + (uint32_t)(lane >> 4);
            #pragma unroll
            for (int mi = 0; mi < 4; mi++) {
                int r = wm + mi * 16 + (lane & 15);
                ldsm4(af[mi][0], af[mi][1], af[mi][2], af[mi][3],
                      sa + (uint32_t)(r * (BK * 2)) + ((kc ^ (uint32_t)(r & 7)) << 4));
            }
            #pragma unroll
            for (int nj = 0; nj < 4; nj++) {
                int r = wn + nj * 16 + (lane & 15);
                ldsm4(bfv[nj][0], bfv[nj][1], bfv[nj][2], bfv[nj][3],
                      sb + (uint32_t)(r * (BK * 2)) + ((kc ^ (uint32_t)(r & 7)) << 4));
            }
            #pragma unroll
            for (int mi = 0; mi < 4; mi++)
                #pragma unroll
                for (int nj = 0; nj < 8; nj++) {
                    int hi = nj >> 1, lo = nj & 1;
                    mma16816(acc[mi][nj],
                             af[mi][0], af[mi][1], af[mi][2], af[mi][3],
                             bfv[hi][lo], bfv[hi][lo + 2]);
                }
        }
        st = (st + 1 == STAGES) ? 0 : st + 1;
    }

    // ---- epilogue: warp covers 64x64 ----
    const int tq = lane >> 2, tr = lane & 3;
    #pragma unroll
    for (int mi = 0; mi < 4; mi++) {
        #pragma unroll
        for (int h = 0; h < 2; h++) {
            int m = m0 + wm + mi * 16 + tq + h * 8;
            float bm = 0.f, rcp = 1.f;
            if (MODE == 0) bm = biasM ? biasM[m] : 0.f;
            if (MODE == 2) rcp = __frcp_rn(rowS[m]);
            #pragma unroll
            for (int nj = 0; nj < 8; nj++) {
                int n = n0 + wn + nj * 8 + tr * 2;
                long long ci = (long long)m * ldc + n;
                if (MODE == 1) {
                    float v0 = __expf(acc[mi][nj][2 * h + 0] * alpha);
                    float v1 = __expf(acc[mi][nj][2 * h + 1] * alpha);
                    *(__nv_bfloat162*)(Cb + ci) = __floats2bfloat162_rn(v0, v1);
                } else if (MODE == 2) {
                    float v0 = acc[mi][nj][2 * h + 0] * rcp;
                    float v1 = acc[mi][nj][2 * h + 1] * rcp;
                    *(__nv_bfloat162*)(Cb + ci) = __floats2bfloat162_rn(v0, v1);
                } else {
                    float v0 = acc[mi][nj][2 * h + 0] * alpha + bm;
                    float v1 = acc[mi][nj][2 * h + 1] * alpha + bm;
                    if (biasN) { v0 += biasN[n]; v1 += biasN[n + 1]; }
                    if (Cf) {
                        if (resid) { v0 += resid[ci]; v1 += resid[ci + 1]; }
                        *(float2*)(Cf + ci) = make_float2(v0, v1);
                    } else {
                        *(__nv_bfloat162*)(Cb + ci) = __floats2bfloat162_rn(v0, v1);
                    }
                }
            }
        }
    }
}

// ------------------- row sums of E: S[row] = sum_j E[row,j] -----------------
__global__ void rowsum_kernel(const bf16* __restrict__ E, float* __restrict__ S)
{
    const __nv_bfloat162* rp = (const __nv_bfloat162*)(E + (long long)blockIdx.x * NPIX);
    const int tid = threadIdx.x;

    float s = 0.f;
    #pragma unroll
    for (int i = 0; i < 8; i++) {
        float2 v = __bfloat1622float2(rp[tid + i * 256]);
        s += v.x + v.y;
    }
    __shared__ float sh[8];
    #pragma unroll
    for (int o = 16; o; o >>= 1) s += __shfl_xor_sync(~0u, s, o);
    if ((tid & 31) == 0) sh[tid >> 5] = s;
    __syncthreads();
    if (tid == 0) {
        float t = sh[0] + sh[1] + sh[2] + sh[3] + sh[4] + sh[5] + sh[6] + sh[7];
        S[blockIdx.x] = t;
    }
}

// ---------------------------------------------------------------------------
extern "C" void kernel_launch(void* const* d_in, const int* in_sizes, int n_in,
                              void* d_out, int out_size)
{
    const float* x     = (const float*)d_in[0];
    const float* gn_w  = (const float*)d_in[1];
    const float* gn_b  = (const float*)d_in[2];
    const float* qkv_w = (const float*)d_in[3];
    const float* qkv_b = (const float*)d_in[4];
    const float* out_w = (const float*)d_in[5];
    const float* out_b = (const float*)d_in[6];
    float* out = (float*)d_out;

    void *p0, *p1, *p2, *p3, *p4, *p5, *p6;
    cudaGetSymbolAddress(&p0, g_hb);
    cudaGetSymbolAddress(&p1, g_w);
    cudaGetSymbolAddress(&p2, g_qk);
    cudaGetSymbolAddress(&p3, g_vt);
    cudaGetSymbolAddress(&p4, g_p);
    cudaGetSymbolAddress(&p5, g_ao);
    cudaGetSymbolAddress(&p6, g_S);
    bf16*  hb = (bf16*)p0;
    bf16*  w  = (bf16*)p1;
    bf16*  qk = (bf16*)p2;
    bf16*  vt = (bf16*)p3;
    bf16*  pb = (bf16*)p4;
    bf16*  ao = (bf16*)p5;
    float* S  = (float*)p6;

    cudaFuncSetAttribute(bgemm_tn<0>, cudaFuncAttributeMaxDynamicSharedMemorySize, GSMEM);
    cudaFuncSetAttribute(bgemm_tn<1>, cudaFuncAttributeMaxDynamicSharedMemorySize, GSMEM);
    cudaFuncSetAttribute(bgemm_tn<2>, cudaFuncAttributeMaxDynamicSharedMemorySize, GSMEM);

    // 0) weights -> bf16
    {
        int n4 = (3 * C_ * C_) / 4;
        f2bf_kernel<<<(n4 + 255) / 256, 256>>>((const float4*)qkv_w, (__nv_bfloat162*)w, n4);
        int m4 = (C_ * C_) / 4;
        f2bf_kernel<<<(m4 + 255) / 256, 256>>>((const float4*)out_w,
                                               (__nv_bfloat162*)(w + 3 * C_ * C_), m4);
    }

    // 1) GroupNorm + transpose -> hb(b,p,c)
    gn_t_kernel<<<B_ * GROUPS, 256>>>(x, gn_w, gn_b, hb);

    // 2) q,k: qk[b,p,o] = sum_c hb[b,p,c] * Wqk[o,c] + qkv_b[o]
    {
        dim3 grid((2 * C_) / BN, NPIX / BM, B_);
        bgemm_tn<0><<<grid, GTHREADS, GSMEM>>>(hb, w, nullptr, qk,
            C_, C_, C_, 2 * C_,
            (long long)NPIX * C_, 0LL, (long long)NPIX * 2 * C_,
            1.0f, nullptr, qkv_b, nullptr, nullptr);
    }

    // 2b) v: vt[b,c,p] = sum_c' Wv[c,c'] * hb[b,p,c'] + qkv_b[1024+c]
    {
        dim3 grid(NPIX / BN, C_ / BM, B_);
        bgemm_tn<0><<<grid, GTHREADS, GSMEM>>>(w + (size_t)2 * C_ * C_, hb, nullptr, vt,
            C_, C_, C_, NPIX,
            0LL, (long long)NPIX * C_, (long long)C_ * NPIX,
            1.0f, qkv_b + 2 * C_, nullptr, nullptr, nullptr);
    }

    // 3) E[b,i,j] = exp(scale * sum_c q[i,c] k[j,c])    (no max-sub; logits ~N(0,1))
    {
        dim3 grid(NPIX / BN, NPIX / BM, B_);
        const float scale = 1.0f / sqrtf((float)C_);
        bgemm_tn<1><<<grid, GTHREADS, GSMEM>>>(qk, qk + C_, nullptr, pb,
            C_, 2 * C_, 2 * C_, NPIX,
            (long long)NPIX * 2 * C_, (long long)NPIX * 2 * C_, (long long)NPIX * NPIX,
            scale, nullptr, nullptr, nullptr, nullptr);
    }

    // 4) row sums S[b,i] = sum_j E[b,i,j]
    rowsum_kernel<<<B_ * NPIX, 256>>>(pb, S);

    // 5) ao[b,i,c] = (1/S[b,i]) * sum_j E[b,i,j] * vt[b,c,j]
    {
        dim3 grid(C_ / BN, NPIX / BM, B_);
        bgemm_tn<2><<<grid, GTHREADS, GSMEM>>>(pb, vt, nullptr, ao,
            NPIX, NPIX, NPIX, C_,
            (long long)NPIX * NPIX, (long long)C_ * NPIX, (long long)NPIX * C_,
            1.0f, nullptr, nullptr, nullptr, S);
    }

    // 6) out[b,o,p] = sum_c Wo[o,c] * ao[b,p,c] + out_b[o] + x[b,o,p]
    {
        dim3 grid(NPIX / BN, C_ / BM, B_);
        bgemm_tn<0><<<grid, GTHREADS, GSMEM>>>(w + (size_t)3 * C_ * C_, ao, out, nullptr,
            C_, C_, C_, NPIX,
            0LL, (long long)NPIX * C_, (long long)C_ * NPIX,
            1.0f, out_b, nullptr, x, nullptr);
    }
}

// round 10
// speedup vs baseline: 1.0595x; 1.0595x over previous
#include <cuda_runtime.h>
#include <cuda_bf16.h>
#include <math.h>
#include <stdint.h>

#define B_    4
#define C_    512
#define NPIX  4096
#define GROUPS 32
#define CPG   16

typedef __nv_bfloat16 bf16;

// ------------------- scratch (__device__ globals; allocation-free) ---------
__device__ bf16  g_hb[(size_t)B_ * NPIX * C_];          // h transposed (b,p,c)
__device__ bf16  g_w [(size_t)(3 * C_ * C_ + C_ * C_)]; // qkv_w ; out_w (bf16)
__device__ bf16  g_qk[(size_t)B_ * NPIX * 2 * C_];      // (b,p,o) o in [0,1024)
__device__ bf16  g_vt[(size_t)B_ * C_ * NPIX];          // (b,c,p)
__device__ bf16  g_p [(size_t)B_ * NPIX * NPIX];        // E = exp(scale*s) (b,i,j)
__device__ bf16  g_ao[(size_t)B_ * NPIX * C_];          // (b,i,c)
__device__ float g_S [(size_t)B_ * NPIX];               // row sums of E

// ------------------------------- helpers -----------------------------------
__device__ __forceinline__ uint32_t smem_u32(const void* p) {
    return (uint32_t)__cvta_generic_to_shared(p);
}
__device__ __forceinline__ void cp16(uint32_t dst, const void* src) {
    asm volatile("cp.async.cg.shared.global [%0], [%1], 16;\n" :: "r"(dst), "l"(src));
}
__device__ __forceinline__ void cp_commit() { asm volatile("cp.async.commit_group;\n"); }
template <int N> __device__ __forceinline__ void cp_wait() {
    asm volatile("cp.async.wait_group %0;\n" :: "n"(N));
}
__device__ __forceinline__ void ldsm4(uint32_t& r0, uint32_t& r1, uint32_t& r2, uint32_t& r3,
                                      uint32_t addr) {
    asm volatile("ldmatrix.sync.aligned.m8n8.x4.shared.b16 {%0,%1,%2,%3}, [%4];\n"
                 : "=r"(r0), "=r"(r1), "=r"(r2), "=r"(r3) : "r"(addr));
}
__device__ __forceinline__ void mma16816(float c[4],
                                         uint32_t a0, uint32_t a1, uint32_t a2, uint32_t a3,
                                         uint32_t b0, uint32_t b1) {
    asm volatile(
        "mma.sync.aligned.m16n8k16.row.col.f32.bf16.bf16.f32 "
        "{%0,%1,%2,%3},{%4,%5,%6,%7},{%8,%9},{%0,%1,%2,%3};\n"
        : "+f"(c[0]), "+f"(c[1]), "+f"(c[2]), "+f"(c[3])
        : "r"(a0), "r"(a1), "r"(a2), "r"(a3), "r"(b0), "r"(b1));
}

// --------------------------- fp32 -> bf16 convert ---------------------------
__global__ void f2bf_kernel(const float4* __restrict__ a, __nv_bfloat162* __restrict__ o, int n4)
{
    int i = blockIdx.x * 256 + threadIdx.x;
    if (i < n4) {
        float4 v = a[i];
        o[2 * i + 0] = __floats2bfloat162_rn(v.x, v.y);
        o[2 * i + 1] = __floats2bfloat162_rn(v.z, v.w);
    }
}

// --------------- GroupNorm + transpose: x(b,c,p) -> hb(b,p,c) bf16 ----------
__global__ void gn_t_kernel(const float* __restrict__ x,
                            const float* __restrict__ gw,
                            const float* __restrict__ gb,
                            bf16* __restrict__ hb)
{
    const int grp = blockIdx.x;
    const int b   = grp >> 5;
    const int g   = grp & 31;
    const float* xg = x + (size_t)grp * (CPG * NPIX);
    const int tid = threadIdx.x;

    float s = 0.f, ss = 0.f;
    const float4* x4 = (const float4*)xg;
    #pragma unroll 4
    for (int i = tid; i < (CPG * NPIX) / 4; i += 256) {
        float4 v = x4[i];
        s  += v.x + v.y + v.z + v.w;
        ss += v.x * v.x + v.y * v.y + v.z * v.z + v.w * v.w;
    }
    __shared__ float sh[64];
    #pragma unroll
    for (int o = 16; o; o >>= 1) {
        s  += __shfl_xor_sync(~0u, s, o);
        ss += __shfl_xor_sync(~0u, ss, o);
    }
    if ((tid & 31) == 0) { sh[tid >> 5] = s; sh[(tid >> 5) + 32] = ss; }
    __syncthreads();
    __shared__ float s_mu, s_rs;
    if (tid < 32) {
        float a = (tid < 8) ? sh[tid]      : 0.f;
        float c = (tid < 8) ? sh[tid + 32] : 0.f;
        #pragma unroll
        for (int o = 4; o; o >>= 1) {
            a += __shfl_xor_sync(~0u, a, o);
            c += __shfl_xor_sync(~0u, c, o);
        }
        if (tid == 0) {
            float mu  = a / (float)(CPG * NPIX);
            float var = c / (float)(CPG * NPIX) - mu * mu;
            s_mu = mu;
            s_rs = rsqrtf(var + 1e-5f);
        }
    }
    __syncthreads();

    __shared__ float s_sc[CPG], s_sb[CPG];
    if (tid < CPG) {
        float w = gw[g * CPG + tid] * s_rs;
        s_sc[tid] = w;
        s_sb[tid] = gb[g * CPG + tid] - s_mu * w;
    }
    __syncthreads();

    for (int p = tid; p < NPIX; p += 256) {
        __nv_bfloat162 pk[8];
        #pragma unroll
        for (int c2 = 0; c2 < 8; c2++) {
            float v0 = xg[(2 * c2 + 0) * NPIX + p] * s_sc[2 * c2 + 0] + s_sb[2 * c2 + 0];
            float v1 = xg[(2 * c2 + 1) * NPIX + p] * s_sc[2 * c2 + 1] + s_sb[2 * c2 + 1];
            pk[c2] = __floats2bfloat162_rn(v0, v1);
        }
        uint4* dst = (uint4*)(hb + ((size_t)(b * NPIX + p)) * C_ + g * CPG);
        dst[0] = *(uint4*)&pk[0];
        dst[1] = *(uint4*)&pk[4];
    }
}

// ------------- TN bf16 GEMM, mma.sync, 64x64 warp tile, 128 thr -------------
// MODE 0: normal (fp32 out w/ resid, or bf16 out, biases)
// MODE 1: bf16 out = exp(alpha * acc), atomic row sums into rowS
// MODE 2: bf16 out = acc * (1 / rowS[m])
#define BM 128
#define BN 128
#define BK 64
#define STAGES 3
#define ATILE (BM * BK)
#define STAGE_ELEMS ((BM + BN) * BK)
#define STAGE_BYTES (STAGE_ELEMS * 2)      // 32768
#define GTHREADS 128
#define GSMEM (STAGES * STAGE_BYTES)       // 98304 -> 2 CTAs/SM (smem-limited)

#define LOAD_STAGE(s_, kt_) do {                                                     \
    bf16* as_ = smem + (s_) * STAGE_ELEMS;                                           \
    bf16* bs_ = as_ + ATILE;                                                         \
    const bf16* ga_ = A  + (long long)(kt_) * BK + lchunk * 8;                       \
    const bf16* gb_ = Bm + (long long)(kt_) * BK + lchunk * 8;                       \
    _Pragma("unroll")                                                                \
    for (int p_ = 0; p_ < 8; p_++) {                                                 \
        int r_ = lrow + p_ * 16;                                                     \
        int sw_ = (lchunk ^ (r_ & 7)) << 4;                                          \
        cp16(smem_u32(as_) + (uint32_t)(r_ * (BK * 2)) + sw_,                        \
             ga_ + (long long)(m0 + r_) * lda);                                      \
        cp16(smem_u32(bs_) + (uint32_t)(r_ * (BK * 2)) + sw_,                        \
             gb_ + (long long)(n0 + r_) * ldb);                                      \
    }                                                                                \
} while (0)

template <int MODE>
__global__ void __launch_bounds__(GTHREADS)
bgemm_tn(const bf16* __restrict__ A, const bf16* __restrict__ Bm,
         float* __restrict__ Cf, bf16* __restrict__ Cb,
         int K, int lda, int ldb, int ldc,
         long long bA, long long bB, long long bC,
         float alpha,
         const float* __restrict__ biasM, const float* __restrict__ biasN,
         const float* __restrict__ resid,
         float* __restrict__ rowS)
{
    extern __shared__ bf16 smem[];

    const int bz = blockIdx.z;
    A  += (long long)bz * bA;
    Bm += (long long)bz * bB;
    if (Cf)    Cf    += (long long)bz * bC;
    if (Cb)    Cb    += (long long)bz * bC;
    if (resid) resid += (long long)bz * bC;
    if (MODE == 1 || MODE == 2) rowS += (long long)bz * NPIX;

    const int m0   = blockIdx.y * BM;
    const int n0   = blockIdx.x * BN;
    const int tid  = threadIdx.x;
    const int lane = tid & 31;
    const int wid  = tid >> 5;           // 0..3
    const int wm   = (wid & 1) * 64;     // warp m-offset
    const int wn   = (wid >> 1) * 64;    // warp n-offset
    const int lrow   = tid >> 3;         // 0..15
    const int lchunk = tid & 7;          // 0..7
    const int nk = K / BK;

    // preload stages 0,1
    LOAD_STAGE(0, 0);
    cp_commit();
    if (nk > 1) LOAD_STAGE(1, 1);
    cp_commit();

    float acc[4][8][4] = {};

    int st = 0;
    for (int kt = 0; kt < nk; kt++) {
        cp_wait<STAGES - 2>();
        __syncthreads();                  // tile kt visible; stage (kt+2)%3 free

        if (kt + 2 < nk) LOAD_STAGE((kt + 2) % STAGES, kt + 2);
        cp_commit();

        const bf16* as = smem + st * STAGE_ELEMS;
        const bf16* bs = as + ATILE;
        const uint32_t sa = smem_u32(as);
        const uint32_t sb = smem_u32(bs);

        #pragma unroll
        for (int ks = 0; ks < 4; ks++) {
            uint32_t af[4][4], bfv[4][4];
            const uint32_t kc = (uint32_t)(ks * 2) + (uint32_t)(lane >> 4);
            #pragma unroll
            for (int mi = 0; mi < 4; mi++) {
                int r = wm + mi * 16 + (lane & 15);
                ldsm4(af[mi][0], af[mi][1], af[mi][2], af[mi][3],
                      sa + (uint32_t)(r * (BK * 2)) + ((kc ^ (uint32_t)(r & 7)) << 4));
            }
            #pragma unroll
            for (int nj = 0; nj < 4; nj++) {
                int r = wn + nj * 16 + (lane & 15);
                ldsm4(bfv[nj][0], bfv[nj][1], bfv[nj][2], bfv[nj][3],
                      sb + (uint32_t)(r * (BK * 2)) + ((kc ^ (uint32_t)(r & 7)) << 4));
            }
            #pragma unroll
            for (int mi = 0; mi < 4; mi++)
                #pragma unroll
                for (int nj = 0; nj < 8; nj++) {
                    int hi = nj >> 1, lo = nj & 1;
                    mma16816(acc[mi][nj],
                             af[mi][0], af[mi][1], af[mi][2], af[mi][3],
                             bfv[hi][lo], bfv[hi][lo + 2]);
                }
        }
        st = (st + 1 == STAGES) ? 0 : st + 1;
    }

    // ---- epilogue: warp covers 64x64 ----
    const int tq = lane >> 2, tr = lane & 3;
    #pragma unroll
    for (int mi = 0; mi < 4; mi++) {
        #pragma unroll
        for (int h = 0; h < 2; h++) {
            int m = m0 + wm + mi * 16 + tq + h * 8;
            float bm = 0.f, rcp = 1.f;
            if (MODE == 0) bm = biasM ? biasM[m] : 0.f;
            if (MODE == 2) rcp = __frcp_rn(rowS[m]);
            float rsum = 0.f;
            #pragma unroll
            for (int nj = 0; nj < 8; nj++) {
                int n = n0 + wn + nj * 8 + tr * 2;
                long long ci = (long long)m * ldc + n;
                if (MODE == 1) {
                    float v0 = __expf(acc[mi][nj][2 * h + 0] * alpha);
                    float v1 = __expf(acc[mi][nj][2 * h + 1] * alpha);
                    rsum += v0 + v1;
                    *(__nv_bfloat162*)(Cb + ci) = __floats2bfloat162_rn(v0, v1);
                } else if (MODE == 2) {
                    float v0 = acc[mi][nj][2 * h + 0] * rcp;
                    float v1 = acc[mi][nj][2 * h + 1] * rcp;
                    *(__nv_bfloat162*)(Cb + ci) = __floats2bfloat162_rn(v0, v1);
                } else {
                    float v0 = acc[mi][nj][2 * h + 0] * alpha + bm;
                    float v1 = acc[mi][nj][2 * h + 1] * alpha + bm;
                    if (biasN) { v0 += biasN[n]; v1 += biasN[n + 1]; }
                    if (Cf) {
                        if (resid) { v0 += resid[ci]; v1 += resid[ci + 1]; }
                        *(float2*)(Cf + ci) = make_float2(v0, v1);
                    } else {
                        *(__nv_bfloat162*)(Cb + ci) = __floats2bfloat162_rn(v0, v1);
                    }
                }
            }
            if (MODE == 1) {
                // reduce the warp's 64-column partial across the 4 lanes of this row
                rsum += __shfl_xor_sync(~0u, rsum, 1);
                rsum += __shfl_xor_sync(~0u, rsum, 2);
                if (tr == 0) atomicAdd(rowS + m, rsum);
            }
        }
    }
}

// ---------------------------------------------------------------------------
extern "C" void kernel_launch(void* const* d_in, const int* in_sizes, int n_in,
                              void* d_out, int out_size)
{
    const float* x     = (const float*)d_in[0];
    const float* gn_w  = (const float*)d_in[1];
    const float* gn_b  = (const float*)d_in[2];
    const float* qkv_w = (const float*)d_in[3];
    const float* qkv_b = (const float*)d_in[4];
    const float* out_w = (const float*)d_in[5];
    const float* out_b = (const float*)d_in[6];
    float* out = (float*)d_out;

    void *p0, *p1, *p2, *p3, *p4, *p5, *p6;
    cudaGetSymbolAddress(&p0, g_hb);
    cudaGetSymbolAddress(&p1, g_w);
    cudaGetSymbolAddress(&p2, g_qk);
    cudaGetSymbolAddress(&p3, g_vt);
    cudaGetSymbolAddress(&p4, g_p);
    cudaGetSymbolAddress(&p5, g_ao);
    cudaGetSymbolAddress(&p6, g_S);
    bf16*  hb = (bf16*)p0;
    bf16*  w  = (bf16*)p1;
    bf16*  qk = (bf16*)p2;
    bf16*  vt = (bf16*)p3;
    bf16*  pb = (bf16*)p4;
    bf16*  ao = (bf16*)p5;
    float* S  = (float*)p6;

    cudaFuncSetAttribute(bgemm_tn<0>, cudaFuncAttributeMaxDynamicSharedMemorySize, GSMEM);
    cudaFuncSetAttribute(bgemm_tn<1>, cudaFuncAttributeMaxDynamicSharedMemorySize, GSMEM);
    cudaFuncSetAttribute(bgemm_tn<2>, cudaFuncAttributeMaxDynamicSharedMemorySize, GSMEM);

    // 0) weights -> bf16 ; zero row-sum accumulator
    {
        int n4 = (3 * C_ * C_) / 4;
        f2bf_kernel<<<(n4 + 255) / 256, 256>>>((const float4*)qkv_w, (__nv_bfloat162*)w, n4);
        int m4 = (C_ * C_) / 4;
        f2bf_kernel<<<(m4 + 255) / 256, 256>>>((const float4*)out_w,
                                               (__nv_bfloat162*)(w + 3 * C_ * C_), m4);
        cudaMemsetAsync(S, 0, (size_t)B_ * NPIX * sizeof(float));
    }

    // 1) GroupNorm + transpose -> hb(b,p,c)
    gn_t_kernel<<<B_ * GROUPS, 256>>>(x, gn_w, gn_b, hb);

    // 2) q,k: qk[b,p,o] = sum_c hb[b,p,c] * Wqk[o,c] + qkv_b[o]
    {
        dim3 grid((2 * C_) / BN, NPIX / BM, B_);
        bgemm_tn<0><<<grid, GTHREADS, GSMEM>>>(hb, w, nullptr, qk,
            C_, C_, C_, 2 * C_,
            (long long)NPIX * C_, 0LL, (long long)NPIX * 2 * C_,
            1.0f, nullptr, qkv_b, nullptr, nullptr);
    }

    // 2b) v: vt[b,c,p] = sum_c' Wv[c,c'] * hb[b,p,c'] + qkv_b[1024+c]
    {
        dim3 grid(NPIX / BN, C_ / BM, B_);
        bgemm_tn<0><<<grid, GTHREADS, GSMEM>>>(w + (size_t)2 * C_ * C_, hb, nullptr, vt,
            C_, C_, C_, NPIX,
            0LL, (long long)NPIX * C_, (long long)C_ * NPIX,
            1.0f, qkv_b + 2 * C_, nullptr, nullptr, nullptr);
    }

    // 3) E[b,i,j] = exp(scale * q.k) ; S[b,i] += row sums (atomic, in epilogue)
    {
        dim3 grid(NPIX / BN, NPIX / BM, B_);
        const float scale = 1.0f / sqrtf((float)C_);
        bgemm_tn<1><<<grid, GTHREADS, GSMEM>>>(qk, qk + C_, nullptr, pb,
            C_, 2 * C_, 2 * C_, NPIX,
            (long long)NPIX * 2 * C_, (long long)NPIX * 2 * C_, (long long)NPIX * NPIX,
            scale, nullptr, nullptr, nullptr, S);
    }

    // 4) ao[b,i,c] = (1/S[b,i]) * sum_j E[b,i,j] * vt[b,c,j]
    {
        dim3 grid(C_ / BN, NPIX / BM, B_);
        bgemm_tn<2><<<grid, GTHREADS, GSMEM>>>(pb, vt, nullptr, ao,
            NPIX, NPIX, NPIX, C_,
            (long long)NPIX * NPIX, (long long)C_ * NPIX, (long long)NPIX * C_,
            1.0f, nullptr, nullptr, nullptr, S);
    }

    // 5) out[b,o,p] = sum_c Wo[o,c] * ao[b,p,c] + out_b[o] + x[b,o,p]
    {
        dim3 grid(NPIX / BN, C_ / BM, B_);
        bgemm_tn<0><<<grid, GTHREADS, GSMEM>>>(w + (size_t)3 * C_ * C_, ao, out, nullptr,
            C_, C_, C_, NPIX,
            0LL, (long long)NPIX * C_, (long long)C_ * NPIX,
            1.0f, out_b, nullptr, x, nullptr);
    }
}